// round 1
// baseline (speedup 1.0000x reference)
#include <cuda_runtime.h>
#include <cstdint>

// Problem constants (N taken from in_sizes for robustness)
#define S_HEADS 64
#define Q_QUBITS 50
#define P_PAULI 3
#define TILE_N 64          // words per block (32 f32x2 pairs)
#define THREADS 256
#define ROWS (Q_QUBITS * P_PAULI)   // 150
#define ROW_STRIDE_F 66             // floats per shared row (even -> 8B aligned pairs, 2-way store conflicts)
#define ROW_STRIDE_U64 33
#define MAX_BLOCKS 4096

// Precomputed tables + partial sums (scratch must be __device__ globals, no allocation)
__device__ float4 g_heads4[Q_QUBITS * S_HEADS];   // [q][s] = (h0,h1,h2,0) normalized
__device__ float  g_hr[S_HEADS];
__device__ float  g_partials[MAX_BLOCKS];

// ---------- f32x2 packed helpers ----------
__device__ __forceinline__ unsigned long long dup2(float x) {
    unsigned long long d;
    unsigned int u = __float_as_uint(x);
    asm("mov.b64 %0, {%1, %1};" : "=l"(d) : "r"(u));
    return d;
}
__device__ __forceinline__ unsigned long long mul2(unsigned long long a, unsigned long long b) {
    unsigned long long d;
    asm("mul.rn.f32x2 %0, %1, %2;" : "=l"(d) : "l"(a), "l"(b));
    return d;
}
__device__ __forceinline__ unsigned long long fma2(unsigned long long a, unsigned long long b, unsigned long long c) {
    unsigned long long d;
    asm("fma.rn.f32x2 %0, %1, %2, %3;" : "=l"(d) : "l"(a), "l"(b), "l"(c));
    return d;
}
__device__ __forceinline__ void unpack2(unsigned long long v, float& lo, float& hi) {
    unsigned int a, b;
    asm("mov.b64 {%0, %1}, %2;" : "=r"(a), "=r"(b) : "l"(v));
    lo = __uint_as_float(a);
    hi = __uint_as_float(b);
}

__device__ __forceinline__ float softplus20(float x) {
    float y = 20.0f * x;
    return fmaxf(y, 0.0f) + log1pf(expf(-fabsf(y)));
}

// ---------- setup: normalize heads + head ratios ----------
__global__ void setup_kernel(const float* __restrict__ heads_param,
                             const float* __restrict__ hr_param) {
    int t = threadIdx.x;
    for (int cell = t; cell < S_HEADS * Q_QUBITS; cell += THREADS) {
        int s = cell / Q_QUBITS;
        int q = cell % Q_QUBITS;
        const float* src = heads_param + (s * Q_QUBITS + q) * P_PAULI;
        float h0 = softplus20(src[0]);
        float h1 = softplus20(src[1]);
        float h2 = softplus20(src[2]);
        float d = fmaxf(h0 + h1 + h2, 1e-12f);
        float inv = 1.0f / d;
        g_heads4[q * S_HEADS + s] = make_float4(h0 * inv, h1 * inv, h2 * inv, 0.0f);
    }
    __shared__ float sv[S_HEADS];
    __shared__ float stot;
    if (t < S_HEADS) sv[t] = softplus20(hr_param[t]);
    __syncthreads();
    if (t == 0) {
        float acc = 0.0f;
        for (int i = 0; i < S_HEADS; i++) acc += sv[i];
        stot = fmaxf(acc, 1e-12f);
    }
    __syncthreads();
    if (t < S_HEADS)
        g_hr[t] = (sv[t] / stot + 0.001f / (float)S_HEADS) / 1.001f;
}

// ---------- main compute kernel ----------
__global__ void __launch_bounds__(THREADS)
compute_kernel(const float* __restrict__ pauli,
               const float* __restrict__ coeff,
               int N) {
    // pauli tile, transposed: [row = 3q+p][n], stride 66 floats (33 u64)
    __shared__ unsigned long long sp64[ROWS * ROW_STRIDE_U64];
    __shared__ float warpSums[8];

    const int tid = threadIdx.x;
    const int tile0 = blockIdx.x * TILE_N;

    // ---- load + transpose (coalesced global reads, 2-way smem store conflicts) ----
    float* spf = (float*)sp64;
    const float* gbase = pauli + (size_t)tile0 * ROWS;
    for (int idx = tid; idx < TILE_N * ROWS; idx += THREADS) {
        int n = idx / ROWS;
        int r = idx - n * ROWS;
        float v = (tile0 + n < N) ? gbase[idx] : 0.0f;
        spf[r * ROW_STRIDE_F + n] = v;
    }
    __syncthreads();

    // ---- compute: warp owns 8 n (4 pairs) x all 64 s; lane owns heads (s0, s0+1) ----
    const int lane = tid & 31;
    const int warpId = tid >> 5;
    const int s0 = lane << 1;
    const unsigned long long* sbase = sp64 + warpId * 4;

    unsigned long long prodA[4], prodB[4];
#pragma unroll
    for (int j = 0; j < 4; j++) {
        prodA[j] = dup2(1.0f);
        prodB[j] = dup2(1.0f);
    }

    const float4* __restrict__ hptr = g_heads4 + s0;

#pragma unroll 2
    for (int q = 0; q < Q_QUBITS; q++) {
        float4 ha = __ldg(&hptr[q * S_HEADS]);
        float4 hb = __ldg(&hptr[q * S_HEADS + 1]);
        unsigned long long ha0 = dup2(ha.x), ha1 = dup2(ha.y), ha2 = dup2(ha.z);
        unsigned long long hb0 = dup2(hb.x), hb1 = dup2(hb.y), hb2 = dup2(hb.z);
        const unsigned long long* r = sbase + q * (3 * ROW_STRIDE_U64);
#pragma unroll
        for (int j = 0; j < 4; j++) {
            unsigned long long p0 = r[j];
            unsigned long long p1 = r[ROW_STRIDE_U64 + j];
            unsigned long long p2 = r[2 * ROW_STRIDE_U64 + j];
            unsigned long long dA = mul2(p0, ha0);
            dA = fma2(p1, ha1, dA);
            dA = fma2(p2, ha2, dA);
            prodA[j] = mul2(prodA[j], dA);
            unsigned long long dB = mul2(p0, hb0);
            dB = fma2(p1, hb1, dB);
            dB = fma2(p2, hb2, dB);
            prodB[j] = mul2(prodB[j], dB);
        }
    }

    // ---- hr-weighted sum over s (butterfly across the warp), then coeff^2/cov ----
    const float hr0 = g_hr[s0];
    const float hr1 = g_hr[s0 + 1];
    float term = 0.0f;   // identical on all lanes after butterflies
#pragma unroll
    for (int j = 0; j < 4; j++) {
        float a0, a1, b0, b1;
        unpack2(prodA[j], a0, a1);
        unpack2(prodB[j], b0, b1);
        float wlo = hr0 * a0 + hr1 * b0;   // word n_base + 2j
        float whi = hr0 * a1 + hr1 * b1;   // word n_base + 2j + 1
#pragma unroll
        for (int off = 16; off > 0; off >>= 1) {
            wlo += __shfl_xor_sync(0xFFFFFFFFu, wlo, off);
            whi += __shfl_xor_sync(0xFFFFFFFFu, whi, off);
        }
        int n0 = tile0 + warpId * 8 + 2 * j;
        if (n0 < N) {
            float c = __ldg(&coeff[n0]);
            term += c * c / wlo;
        }
        if (n0 + 1 < N) {
            float c = __ldg(&coeff[n0 + 1]);
            term += c * c / whi;
        }
    }
    if (lane == 0) warpSums[warpId] = term;
    __syncthreads();
    if (tid == 0) {
        float s = 0.0f;
#pragma unroll
        for (int i = 0; i < 8; i++) s += warpSums[i];
        g_partials[blockIdx.x] = s;
    }
}

// ---------- deterministic final reduction ----------
__global__ void reduce_kernel(int nblocks, float* __restrict__ out) {
    __shared__ double sdata[THREADS];
    double s = 0.0;
    for (int i = threadIdx.x; i < nblocks; i += THREADS)
        s += (double)g_partials[i];
    sdata[threadIdx.x] = s;
    __syncthreads();
    for (int st = THREADS / 2; st > 0; st >>= 1) {
        if (threadIdx.x < st) sdata[threadIdx.x] += sdata[threadIdx.x + st];
        __syncthreads();
    }
    if (threadIdx.x == 0) out[0] = (float)sdata[0];
}

extern "C" void kernel_launch(void* const* d_in, const int* in_sizes, int n_in,
                              void* d_out, int out_size) {
    const float* pauli = (const float*)d_in[0];   // [N, 50, 3] fp32
    const float* coeff = (const float*)d_in[1];   // [N]
    const float* hp    = (const float*)d_in[2];   // [64, 50, 3]
    const float* hrp   = (const float*)d_in[3];   // [64]
    int N = in_sizes[1];

    setup_kernel<<<1, THREADS>>>(hp, hrp);
    int nblocks = (N + TILE_N - 1) / TILE_N;
    compute_kernel<<<nblocks, THREADS>>>(pauli, coeff, N);
    reduce_kernel<<<1, THREADS>>>(nblocks, (float*)d_out);
}

// round 4
// speedup vs baseline: 1.1037x; 1.1037x over previous
#include <cuda_runtime.h>
#include <cstdint>

#define S_HEADS 64
#define Q_QUBITS 50
#define P_PAULI 3
#define TILE_N 64          // words per block (32 f32x2 pairs)
#define THREADS 256
#define ROWS (Q_QUBITS * P_PAULI)   // 150
#define ROW_STRIDE_F 66             // floats per shared row (even -> 8B-aligned pairs)
#define ROW_STRIDE_U64 33
#define MAX_BLOCKS 4096

// Scratch (__device__ globals; no allocation allowed)
// SoA duplicated-head tables: g_hd[p][q][s] = (h_p[s], h_p[s]) packed as u64.
// A lane owning heads (s0, s0+1) loads one ulonglong2 per p -> both heads.
__device__ unsigned long long g_h0[Q_QUBITS * S_HEADS];
__device__ unsigned long long g_h1[Q_QUBITS * S_HEADS];
__device__ unsigned long long g_h2[Q_QUBITS * S_HEADS];
__device__ float  g_hr[S_HEADS];
__device__ float  g_partials[MAX_BLOCKS];
__device__ unsigned int g_count = 0;

// ---------- f32x2 packed helpers ----------
__device__ __forceinline__ unsigned long long mul2(unsigned long long a, unsigned long long b) {
    unsigned long long d;
    asm("mul.rn.f32x2 %0, %1, %2;" : "=l"(d) : "l"(a), "l"(b));
    return d;
}
__device__ __forceinline__ unsigned long long fma2(unsigned long long a, unsigned long long b, unsigned long long c) {
    unsigned long long d;
    asm("fma.rn.f32x2 %0, %1, %2, %3;" : "=l"(d) : "l"(a), "l"(b), "l"(c));
    return d;
}
__device__ __forceinline__ void unpack2(unsigned long long v, float& lo, float& hi) {
    unsigned int a, b;
    asm("mov.b64 {%0, %1}, %2;" : "=r"(a), "=r"(b) : "l"(v));
    lo = __uint_as_float(a);
    hi = __uint_as_float(b);
}
__device__ __forceinline__ unsigned long long dup2(float x) {
    unsigned long long d;
    unsigned int u = __float_as_uint(x);
    asm("mov.b64 %0, {%1, %1};" : "=l"(d) : "r"(u));
    return d;
}

__device__ __forceinline__ float softplus20(float x) {
    float y = 20.0f * x;
    return fmaxf(y, 0.0f) + log1pf(expf(-fabsf(y)));   // accurate expf
}

// ---------- setup: normalize heads into SoA dup tables + head ratios ----------
// grid = 13 blocks x 256 (3200 head cells); block 0 also computes hr.
__global__ void setup_kernel(const float* __restrict__ heads_param,
                             const float* __restrict__ hr_param) {
    int cell = blockIdx.x * THREADS + threadIdx.x;   // cell = s*Q + q
    if (cell < S_HEADS * Q_QUBITS) {
        int s = cell / Q_QUBITS;
        int q = cell - s * Q_QUBITS;
        const float* src = heads_param + cell * P_PAULI;
        float h0 = softplus20(src[0]);
        float h1 = softplus20(src[1]);
        float h2 = softplus20(src[2]);
        float inv = 1.0f / fmaxf(h0 + h1 + h2, 1e-12f);
        int idx = q * S_HEADS + s;
        g_h0[idx] = dup2(h0 * inv);
        g_h1[idx] = dup2(h1 * inv);
        g_h2[idx] = dup2(h2 * inv);
    }
    if (blockIdx.x == 0) {
        __shared__ float sv[S_HEADS];
        __shared__ float stot;
        int t = threadIdx.x;
        if (t < S_HEADS) sv[t] = softplus20(hr_param[t]);
        __syncthreads();
        if (t == 0) {
            float acc = 0.0f;
            for (int i = 0; i < S_HEADS; i++) acc += sv[i];
            stot = fmaxf(acc, 1e-12f);
        }
        __syncthreads();
        if (t < S_HEADS)
            g_hr[t] = (sv[t] / stot + 0.001f / (float)S_HEADS) / 1.001f;
    }
}

// ---------- main compute kernel (final reduction fused via last-block pattern) ----------
__global__ void __launch_bounds__(THREADS)
compute_kernel(const float* __restrict__ pauli,
               const float* __restrict__ coeff,
               int N, int nblocks, float* __restrict__ out) {
    // pauli tile, transposed: [row = 3q+p][n], stride 66 floats (33 u64)
    __shared__ unsigned long long sp64[ROWS * ROW_STRIDE_U64];
    __shared__ float warpSums[8];
    __shared__ bool isLast;
    __shared__ double sred[THREADS];

    const int tid = threadIdx.x;
    const int tile0 = blockIdx.x * TILE_N;

    // ---- load + transpose (coalesced global reads) ----
    float* spf = (float*)sp64;
    const float* gbase = pauli + (size_t)tile0 * ROWS;
    for (int idx = tid; idx < TILE_N * ROWS; idx += THREADS) {
        int n = idx / ROWS;
        int r = idx - n * ROWS;
        float v = (tile0 + n < N) ? gbase[idx] : 0.0f;
        spf[r * ROW_STRIDE_F + n] = v;
    }
    __syncthreads();

    // ---- compute: warp owns 8 n (4 f32x2 pairs) x all 64 s; lane owns heads (s0, s0+1) ----
    const int lane = tid & 31;
    const int warpId = tid >> 5;
    const unsigned long long* sbase = sp64 + warpId * 4;

    unsigned long long prodA[4], prodB[4];
#pragma unroll
    for (int j = 0; j < 4; j++) {
        prodA[j] = 0x3F8000003F800000ULL;   // (1.0f, 1.0f)
        prodB[j] = 0x3F8000003F800000ULL;
    }

    // lane reads g_h?[q*64 + 2*lane .. +1] -> one LDG.128 per p covers both heads
    const ulonglong2* __restrict__ h0p = (const ulonglong2*)(g_h0) + lane;
    const ulonglong2* __restrict__ h1p = (const ulonglong2*)(g_h1) + lane;
    const ulonglong2* __restrict__ h2p = (const ulonglong2*)(g_h2) + lane;

#pragma unroll 2
    for (int q = 0; q < Q_QUBITS; q++) {
        ulonglong2 h0 = __ldg(&h0p[q * (S_HEADS / 2)]);   // .x = head s0, .y = head s0+1 (dup pairs)
        ulonglong2 h1 = __ldg(&h1p[q * (S_HEADS / 2)]);
        ulonglong2 h2 = __ldg(&h2p[q * (S_HEADS / 2)]);
        const unsigned long long* r = sbase + q * (3 * ROW_STRIDE_U64);
#pragma unroll
        for (int j = 0; j < 4; j++) {
            unsigned long long p0 = r[j];
            unsigned long long p1 = r[ROW_STRIDE_U64 + j];
            unsigned long long p2 = r[2 * ROW_STRIDE_U64 + j];
            // all-nonnegative direct dot: no cancellation
            unsigned long long dA = mul2(p0, h0.x);
            dA = fma2(p1, h1.x, dA);
            dA = fma2(p2, h2.x, dA);
            prodA[j] = mul2(prodA[j], dA);
            unsigned long long dB = mul2(p0, h0.y);
            dB = fma2(p1, h1.y, dB);
            dB = fma2(p2, h2.y, dB);
            prodB[j] = mul2(prodB[j], dB);
        }
    }

    // ---- hr-weighted sum over s (warp butterfly), then coeff^2/cov ----
    const int s0 = lane << 1;
    const float hr0 = g_hr[s0];
    const float hr1 = g_hr[s0 + 1];
    float term = 0.0f;
#pragma unroll
    for (int j = 0; j < 4; j++) {
        float a0, a1, b0, b1;
        unpack2(prodA[j], a0, a1);
        unpack2(prodB[j], b0, b1);
        float wlo = hr0 * a0 + hr1 * b0;   // word n_base + 2j
        float whi = hr0 * a1 + hr1 * b1;   // word n_base + 2j + 1
#pragma unroll
        for (int off = 16; off > 0; off >>= 1) {
            wlo += __shfl_xor_sync(0xFFFFFFFFu, wlo, off);
            whi += __shfl_xor_sync(0xFFFFFFFFu, whi, off);
        }
        int n0 = tile0 + warpId * 8 + 2 * j;
        if (n0 < N) {
            float c = __ldg(&coeff[n0]);
            term += c * c / wlo;
        }
        if (n0 + 1 < N) {
            float c = __ldg(&coeff[n0 + 1]);
            term += c * c / whi;
        }
    }
    if (lane == 0) warpSums[warpId] = term;
    __syncthreads();
    if (tid == 0) {
        float s = 0.0f;
#pragma unroll
        for (int i = 0; i < 8; i++) s += warpSums[i];
        g_partials[blockIdx.x] = s;
        __threadfence();
        unsigned int prev = atomicAdd(&g_count, 1u);
        isLast = (prev == (unsigned int)(nblocks - 1));
    }
    __syncthreads();

    // ---- last arriving block: deterministic fixed-order final sum ----
    if (isLast) {
        double s = 0.0;
        for (int i = tid; i < nblocks; i += THREADS) {
            float v;
            asm volatile("ld.global.cg.f32 %0, [%1];" : "=f"(v) : "l"(g_partials + i));
            s += (double)v;
        }
        sred[tid] = s;
        __syncthreads();
        for (int st = THREADS / 2; st > 0; st >>= 1) {
            if (tid < st) sred[tid] += sred[tid + st];
            __syncthreads();
        }
        if (tid == 0) {
            out[0] = (float)sred[0];
            g_count = 0;             // reset for next graph replay
        }
    }
}

extern "C" void kernel_launch(void* const* d_in, const int* in_sizes, int n_in,
                              void* d_out, int out_size) {
    const float* pauli = (const float*)d_in[0];   // [N, 50, 3] fp32
    const float* coeff = (const float*)d_in[1];   // [N]
    const float* hp    = (const float*)d_in[2];   // [64, 50, 3]
    const float* hrp   = (const float*)d_in[3];   // [64]
    int N = in_sizes[1];

    int setupBlocks = (S_HEADS * Q_QUBITS + THREADS - 1) / THREADS;  // 13
    setup_kernel<<<setupBlocks, THREADS>>>(hp, hrp);
    int nblocks = (N + TILE_N - 1) / TILE_N;
    compute_kernel<<<nblocks, THREADS>>>(pauli, coeff, N, nblocks, (float*)d_out);
}

// round 5
// speedup vs baseline: 1.2949x; 1.1732x over previous
#include <cuda_runtime.h>
#include <cstdint>

#define S_HEADS 64
#define Q_QUBITS 50
#define P_PAULI 3
#define TILE_N 64          // words per block (32 f32x2 pairs)
#define THREADS 256
#define ROWS (Q_QUBITS * P_PAULI)   // 150
#define ROW_STRIDE_F 68             // floats per shared row (16B-aligned rows for LDS.128)
#define ROW_STRIDE_U64 34
#define MAX_BLOCKS 4096

// Scratch (__device__ globals; no allocation allowed)
// Non-duplicated SoA head tables: g_fp[q*64 + s] = normalized h_p for head s, qubit q.
__device__ float g_f0[Q_QUBITS * S_HEADS];
__device__ float g_f1[Q_QUBITS * S_HEADS];
__device__ float g_f2[Q_QUBITS * S_HEADS];
__device__ float g_hr[S_HEADS];
__device__ float g_partials[MAX_BLOCKS];
__device__ unsigned int g_count = 0;

// ---------- f32x2 packed helpers ----------
__device__ __forceinline__ unsigned long long mul2(unsigned long long a, unsigned long long b) {
    unsigned long long d;
    asm("mul.rn.f32x2 %0, %1, %2;" : "=l"(d) : "l"(a), "l"(b));
    return d;
}
__device__ __forceinline__ unsigned long long fma2(unsigned long long a, unsigned long long b, unsigned long long c) {
    unsigned long long d;
    asm("fma.rn.f32x2 %0, %1, %2, %3;" : "=l"(d) : "l"(a), "l"(b), "l"(c));
    return d;
}
__device__ __forceinline__ void unpack2(unsigned long long v, float& lo, float& hi) {
    unsigned int a, b;
    asm("mov.b64 {%0, %1}, %2;" : "=r"(a), "=r"(b) : "l"(v));
    lo = __uint_as_float(a);
    hi = __uint_as_float(b);
}
__device__ __forceinline__ unsigned long long dup2(float x) {
    unsigned long long d;
    unsigned int u = __float_as_uint(x);
    asm("mov.b64 %0, {%1, %1};" : "=l"(d) : "r"(u));
    return d;
}

__device__ __forceinline__ float softplus20(float x) {
    float y = 20.0f * x;
    return fmaxf(y, 0.0f) + log1pf(expf(-fabsf(y)));
}

// ---------- setup: normalize heads into SoA tables + head ratios ----------
__global__ void setup_kernel(const float* __restrict__ heads_param,
                             const float* __restrict__ hr_param) {
    int cell = blockIdx.x * THREADS + threadIdx.x;   // cell = s*Q + q
    if (cell < S_HEADS * Q_QUBITS) {
        int s = cell / Q_QUBITS;
        int q = cell - s * Q_QUBITS;
        const float* src = heads_param + cell * P_PAULI;
        float h0 = softplus20(src[0]);
        float h1 = softplus20(src[1]);
        float h2 = softplus20(src[2]);
        float inv = 1.0f / fmaxf(h0 + h1 + h2, 1e-12f);
        int idx = q * S_HEADS + s;
        g_f0[idx] = h0 * inv;
        g_f1[idx] = h1 * inv;
        g_f2[idx] = h2 * inv;
    }
    if (blockIdx.x == 0) {
        __shared__ float sv[S_HEADS];
        __shared__ float stot;
        int t = threadIdx.x;
        if (t < S_HEADS) sv[t] = softplus20(hr_param[t]);
        __syncthreads();
        if (t == 0) {
            float acc = 0.0f;
            for (int i = 0; i < S_HEADS; i++) acc += sv[i];
            stot = fmaxf(acc, 1e-12f);
        }
        __syncthreads();
        if (t < S_HEADS)
            g_hr[t] = (sv[t] / stot + 0.001f / (float)S_HEADS) / 1.001f;
    }
}

// ---------- main compute kernel (final reduction fused via last-block pattern) ----------
__global__ void __launch_bounds__(THREADS)
compute_kernel(const float* __restrict__ pauli,
               const float* __restrict__ coeff,
               int N, int nblocks, float* __restrict__ out) {
    // pauli tile, transposed: [row = 3q+p][n], stride 68 floats (34 u64; rows 16B-aligned)
    __shared__ unsigned long long sp64[ROWS * ROW_STRIDE_U64];
    __shared__ float warpSums[8];
    __shared__ bool isLast;
    __shared__ double sred[THREADS];

    const int tid = threadIdx.x;
    const int tile0 = blockIdx.x * TILE_N;

    // ---- load + transpose: float2 gmem loads (row = 75 float2), strided smem stores ----
    float* spf = (float*)sp64;
    const float2* gbase2 = (const float2*)(pauli + (size_t)tile0 * ROWS);
    const bool fullTile = (tile0 + TILE_N <= N);
    for (int f = tid; f < TILE_N * (ROWS / 2); f += THREADS) {
        int n = f / (ROWS / 2);
        int rp = f - n * (ROWS / 2);        // float-pair index within row
        float2 v = make_float2(0.f, 0.f);
        if (fullTile || tile0 + n < N)
            v = gbase2[(size_t)n * (ROWS / 2) + rp];
        int r = 2 * rp;
        spf[(r + 0) * ROW_STRIDE_F + n] = v.x;
        spf[(r + 1) * ROW_STRIDE_F + n] = v.y;
    }
    __syncthreads();

    // ---- compute: warp owns 8 n (4 f32x2 pairs) x all 64 s; lane owns heads (s0, s0+1) ----
    const int lane = tid & 31;
    const int warpId = tid >> 5;

    unsigned long long prodA[4], prodB[4];
#pragma unroll
    for (int j = 0; j < 4; j++) {
        prodA[j] = 0x3F8000003F800000ULL;   // (1.0f, 1.0f)
        prodB[j] = 0x3F8000003F800000ULL;
    }

    const float2* __restrict__ f0p = (const float2*)g_f0 + lane;   // (h[s0], h[s0+1])
    const float2* __restrict__ f1p = (const float2*)g_f1 + lane;
    const float2* __restrict__ f2p = (const float2*)g_f2 + lane;
    const ulonglong2* __restrict__ rbase = (const ulonglong2*)(sp64) + warpId * 2;

#pragma unroll 5
    for (int q = 0; q < Q_QUBITS; q++) {
        float2 c0 = __ldg(&f0p[q * (S_HEADS / 2)]);
        float2 c1 = __ldg(&f1p[q * (S_HEADS / 2)]);
        float2 c2 = __ldg(&f2p[q * (S_HEADS / 2)]);
        unsigned long long ha0 = dup2(c0.x), hb0 = dup2(c0.y);
        unsigned long long ha1 = dup2(c1.x), hb1 = dup2(c1.y);
        unsigned long long ha2 = dup2(c2.x), hb2 = dup2(c2.y);

        // 3 p-rows x 4 u64, fetched as 6 broadcast LDS.128
        const ulonglong2* rr = rbase + q * (3 * ROW_STRIDE_U64 / 2);   // 51 ull2 per q-group
        ulonglong2 P0a = rr[0],  P0b = rr[1];                           // p0: j0..j3
        ulonglong2 P1a = rr[ROW_STRIDE_U64 / 2],      P1b = rr[ROW_STRIDE_U64 / 2 + 1];
        ulonglong2 P2a = rr[ROW_STRIDE_U64],          P2b = rr[ROW_STRIDE_U64 + 1];

        unsigned long long p0[4] = {P0a.x, P0a.y, P0b.x, P0b.y};
        unsigned long long p1[4] = {P1a.x, P1a.y, P1b.x, P1b.y};
        unsigned long long p2[4] = {P2a.x, P2a.y, P2b.x, P2b.y};
#pragma unroll
        for (int j = 0; j < 4; j++) {
            unsigned long long dA = mul2(p0[j], ha0);
            dA = fma2(p1[j], ha1, dA);
            dA = fma2(p2[j], ha2, dA);
            prodA[j] = mul2(prodA[j], dA);
            unsigned long long dB = mul2(p0[j], hb0);
            dB = fma2(p1[j], hb1, dB);
            dB = fma2(p2[j], hb2, dB);
            prodB[j] = mul2(prodB[j], dB);
        }
    }

    // ---- hr-weighted sum over s (warp butterfly), then coeff^2/cov ----
    const int s0 = lane << 1;
    const float hr0 = g_hr[s0];
    const float hr1 = g_hr[s0 + 1];
    float term = 0.0f;
#pragma unroll
    for (int j = 0; j < 4; j++) {
        float a0, a1, b0, b1;
        unpack2(prodA[j], a0, a1);
        unpack2(prodB[j], b0, b1);
        float wlo = hr0 * a0 + hr1 * b0;   // word n_base + 2j
        float whi = hr0 * a1 + hr1 * b1;   // word n_base + 2j + 1
#pragma unroll
        for (int off = 16; off > 0; off >>= 1) {
            wlo += __shfl_xor_sync(0xFFFFFFFFu, wlo, off);
            whi += __shfl_xor_sync(0xFFFFFFFFu, whi, off);
        }
        int n0 = tile0 + warpId * 8 + 2 * j;
        if (n0 < N) {
            float c = __ldg(&coeff[n0]);
            term += c * c / wlo;
        }
        if (n0 + 1 < N) {
            float c = __ldg(&coeff[n0 + 1]);
            term += c * c / whi;
        }
    }
    if (lane == 0) warpSums[warpId] = term;
    __syncthreads();
    if (tid == 0) {
        float s = 0.0f;
#pragma unroll
        for (int i = 0; i < 8; i++) s += warpSums[i];
        g_partials[blockIdx.x] = s;
        __threadfence();
        unsigned int prev = atomicAdd(&g_count, 1u);
        isLast = (prev == (unsigned int)(nblocks - 1));
    }
    __syncthreads();

    // ---- last arriving block: deterministic fixed-order final sum ----
    if (isLast) {
        double s = 0.0;
        for (int i = tid; i < nblocks; i += THREADS) {
            float v;
            asm volatile("ld.global.cg.f32 %0, [%1];" : "=f"(v) : "l"(g_partials + i));
            s += (double)v;
        }
        sred[tid] = s;
        __syncthreads();
        for (int st = THREADS / 2; st > 0; st >>= 1) {
            if (tid < st) sred[tid] += sred[tid + st];
            __syncthreads();
        }
        if (tid == 0) {
            out[0] = (float)sred[0];
            g_count = 0;             // reset for next graph replay
        }
    }
}

extern "C" void kernel_launch(void* const* d_in, const int* in_sizes, int n_in,
                              void* d_out, int out_size) {
    const float* pauli = (const float*)d_in[0];   // [N, 50, 3] fp32
    const float* coeff = (const float*)d_in[1];   // [N]
    const float* hp    = (const float*)d_in[2];   // [64, 50, 3]
    const float* hrp   = (const float*)d_in[3];   // [64]
    int N = in_sizes[1];

    int setupBlocks = (S_HEADS * Q_QUBITS + THREADS - 1) / THREADS;  // 13
    setup_kernel<<<setupBlocks, THREADS>>>(hp, hrp);
    int nblocks = (N + TILE_N - 1) / TILE_N;
    compute_kernel<<<nblocks, THREADS>>>(pauli, coeff, N, nblocks, (float*)d_out);
}